// round 15
// baseline (speedup 1.0000x reference)
#include <cuda_runtime.h>
#include <cuda_bf16.h>

#define D 256
#define NC 64
#define NB 64
#define MAXN 4096
#define SPG 16
#define TILE 64
#define NT 512
#define FLAG_EPS 3e-6f

typedef unsigned long long ull;
typedef unsigned int u32;

#define FMA2(acc, a, b) asm("fma.rn.f32x2 %0, %1, %2, %0;" : "+l"(acc) : "l"(a), "l"(b))
#define DUP(d, x)       asm("mov.b64 %0, {%1, %1};" : "=l"(d) : "r"(__float_as_uint(x)))
#define CVTBF2(r, lo, hi) asm("cvt.rn.bf16x2.f32 %0, %1, %2;" : "=r"(r) : "f"(hi), "f"(lo))

#define CP16(dst, src) \
    asm volatile("cp.async.cg.shared.global [%0], [%1], 16;" :: "r"(dst), "l"(src))
#define CPCOMMIT() asm volatile("cp.async.commit_group;" ::: "memory")
#define CPWAIT0()  asm volatile("cp.async.wait_group 0;" ::: "memory")

#define LDSM4(r0, r1, r2, r3, addr) \
    asm volatile("ldmatrix.sync.aligned.m8n8.x4.shared.b16 {%0,%1,%2,%3}, [%4];" \
                 : "=r"(r0), "=r"(r1), "=r"(r2), "=r"(r3) : "r"(addr))

#define LDSM4T(r0, r1, r2, r3, addr) \
    asm volatile("ldmatrix.sync.aligned.m8n8.x4.trans.shared.b16 {%0,%1,%2,%3}, [%4];" \
                 : "=r"(r0), "=r"(r1), "=r"(r2), "=r"(r3) : "r"(addr))

#define MMA16816(c, a0, a1, a2, a3, b0, b1) \
    asm volatile("mma.sync.aligned.m16n8k16.row.col.f32.bf16.bf16.f32 " \
                 "{%0,%1,%2,%3}, {%4,%5,%6,%7}, {%8,%9}, {%0,%1,%2,%3};" \
                 : "+f"((c)[0]), "+f"((c)[1]), "+f"((c)[2]), "+f"((c)[3]) \
                 : "r"(a0), "r"(a1), "r"(a2), "r"(a3), "r"(b0), "r"(b1))

__device__ int   g_starts[NB + 1];
__device__ float g_Q[NC * D];
__device__ float g_QtT[D * NC];      // [e][c] (fallback)
__device__ u32   g_QtbfH[NC * 128];  // pre-split bf16-hi Qt, k_main smem layout
__device__ u32   g_QtbfL[NC * 128];
__device__ float g_cK[NC];
__device__ float g_P[NB * NC * D];
__device__ float g_sumA[NB * NC];
__device__ float g_H[NB * NC * D];

__device__ __forceinline__ u32 s2u(const void* p) {
    u32 a;
    asm("{ .reg .u64 t; cvta.to.shared.u64 t, %1; cvt.u32.u64 %0, t; }" : "=r"(a) : "l"(p));
    return a;
}

__device__ __forceinline__ void split2(float v0, float v1, u32& hi, u32& lo) {
    CVTBF2(hi, v0, v1);
    float h0 = __uint_as_float(hi << 16);
    float h1 = __uint_as_float(hi & 0xffff0000u);
    CVTBF2(lo, v0 - h0, v1 - h1);
}

__device__ __forceinline__ int lower_bound_batch(const void* batch, int n, int is32, int val) {
    int lo = 0, hi = n;
    while (lo < hi) {
        int mid = (lo + hi) >> 1;
        long long bv = is32 ? (long long)((const int*)batch)[mid]
                            : ((const long long*)batch)[mid];
        if (bv < (long long)val) lo = mid + 1; else hi = mid;
    }
    return lo;
}

// ---------------- fused setup: meta + zero + Q + Qt + Qt split + mask/argzero ----------------
__global__ __launch_bounds__(256) void k_setup(
    const void* __restrict__ batch, int n,
    const float* __restrict__ Qp,
    const float* __restrict__ Wq, const float* __restrict__ bq,
    const float* __restrict__ Wk, const float* __restrict__ bk,
    float* __restrict__ maskout, float* __restrict__ argout,
    int do_mask, int do_arg) {
    __shared__ float shA[D];
    __shared__ float shQ[D];
    __shared__ int shS[2];
    int c = blockIdx.x, e = threadIdx.x;

    // local starts for this block's graph (mask/argzero) + global table (block 0)
    {
        long long probe = ((const long long*)batch)[n / 4];
        int is32 = (probe < 0 || probe >= NB) ? 1 : 0;
        if (e < 2) shS[e] = lower_bound_batch(batch, n, is32, c + e);
        if (c == 0 && e < NB + 1)
            g_starts[e] = (e < NB) ? lower_bound_batch(batch, n, is32, e) : n;
    }

    // zero g_P slice + g_sumA slice
    {
        float4* pz = (float4*)(g_P + (size_t)c * NC * D);
        float4 z = make_float4(0.f, 0.f, 0.f, 0.f);
        #pragma unroll
        for (int it = 0; it < 16; it++) pz[e + 256 * it] = z;
        if (e < NC) g_sumA[c * NC + e] = 0.f;
    }

    // Q[c][e]
    shA[e] = Qp[c * D + e];
    __syncthreads();

    // mask + argout tail zero for graph c (uses shS)
    {
        int cnt = shS[1] - shS[0];
        for (int idx = e; idx < MAXN; idx += 256) {
            if (do_mask) maskout[(size_t)c * MAXN + idx] = (idx < cnt) ? 1.f : 0.f;
            if (do_arg && idx >= cnt) argout[(size_t)c * MAXN + idx] = 0.f;
        }
    }

    {
        float a0 = 0.f, a1 = 0.f, a2 = 0.f, a3 = 0.f;
        #pragma unroll 4
        for (int k = 0; k < D; k += 4) {
            a0 = fmaf(shA[k + 0], Wq[e * D + k + 0], a0);
            a1 = fmaf(shA[k + 1], Wq[e * D + k + 1], a1);
            a2 = fmaf(shA[k + 2], Wq[e * D + k + 2], a2);
            a3 = fmaf(shA[k + 3], Wq[e * D + k + 3], a3);
        }
        float q = ((a0 + a1) + (a2 + a3)) + bq[e];
        shQ[e] = q;
        g_Q[c * D + e] = q;
    }
    __syncthreads();

    // Qt[c][e]; cK[c]
    {
        float a0 = 0.f, a1 = 0.f;
        #pragma unroll 4
        for (int d = 0; d < D; d += 2) {
            a0 = fmaf(shQ[d + 0], Wk[(d + 0) * D + e], a0);
            a1 = fmaf(shQ[d + 1], Wk[(d + 1) * D + e], a1);
        }
        float v = a0 + a1;
        g_QtT[e * NC + c] = v;
        shA[e] = v;
        if (e == 0) {
            float ck = 0.f;
            for (int d = 0; d < D; d++) ck += shQ[d] * bk[d];
            g_cK[c] = ck;
        }
    }
    __syncthreads();

    // split Qt row -> g_QtbfH/L in k_main's swizzled layout
    if (e < 64) {
        int e4 = e;
        float v0 = shA[4 * e4 + 0], v1 = shA[4 * e4 + 1];
        float v2 = shA[4 * e4 + 2], v3 = shA[4 * e4 + 3];
        u32 h0, l0, h1, l1;
        split2(v0, v1, h0, l0);
        split2(v2, v3, h1, l1);
        int idx = c * 128 + ((2 * e4) ^ ((c & 7) << 2));
        g_QtbfH[idx] = h0; g_QtbfH[idx + 1] = h1;
        g_QtbfL[idx] = l0; g_QtbfL[idx + 1] = l1;
    }
}

// ---------------- main fused kernel (unchanged from R14) ----------------
#define SMEM_FLOATS 57600
extern __shared__ float smem[];

__global__ __launch_bounds__(NT, 1) void k_main(const float* __restrict__ x,
                                                float* __restrict__ argout, int has_arg) {
    float* As   = smem + 32768;
    float* cKs  = smem + 40960;
    float* sAcc = smem + 41024;
    int*   flagn = (int*)(smem + 41088);
    int*   flagl = (int*)(smem + 41089);
    float* rawF = smem + 41216;

    int t = threadIdx.x;
    int g = blockIdx.x / SPG, sl = blockIdx.x % SPG;
    int s0 = g_starts[g], s1 = g_starts[g + 1];
    int cnt = s1 - s0;
    int chunk = (cnt + SPG - 1) / SPG;
    int i0 = s0 + sl * chunk;
    int i1 = min(i0 + chunk, s1);
    if (i0 >= i1) return;  // uniform across block

    u32 sb = s2u(smem);
    const u32 xnH = sb, xnL = sb + 32768;
    const u32 qtH = sb + 65536, qtL = sb + 98304;
    const u32 abH = sb + 147456, abL = sb + 155648;
    const u32 rawU = sb + 41216u * 4u;

    // prologue: prefetch first tile + preconverted Qt (one cp.async group)
    {
        int nbj = min(TILE, i1 - i0);
        for (int r = t; r < nbj * 64; r += NT) {
            int n = r >> 6, e4 = r & 63;
            CP16(rawU + (u32)r * 16u, x + (size_t)(i0 + n) * D + 4 * e4);
        }
        for (int r = t; r < 2048; r += NT) {
            CP16(qtH + (u32)r * 16u, (const char*)g_QtbfH + (size_t)r * 16);
            CP16(qtL + (u32)r * 16u, (const char*)g_QtbfL + (size_t)r * 16);
        }
        CPCOMMIT();
    }

    // init: zero Xnbf, load cK
    for (int r = t; r < 16384; r += NT) ((u32*)smem)[r] = 0u;
    if (t < NC) { cKs[t] = g_cK[t]; sAcc[t] = 0.f; }
    if (t == 0) *flagn = 0;

    const int lane = t & 31;
    const int w    = t >> 5;

    const int cw = w & 3, nw = w >> 2;
    const int pb_arow = 16 * cw + (lane & 7) + 8 * ((lane >> 3) & 1);
    const int pb_ae   = (lane >> 4) & 1;
    const int pb_asw  = (pb_arow & 7) << 4;
    const int pb_brow = 16 * nw + (lane & 7) + 8 * ((lane >> 4) & 1);
    const int pb_be   = (lane >> 3) & 1;
    const int pb_bsw  = (pb_brow & 7) << 4;
    const int wo_c = 16 * cw + (lane >> 2);
    const int wo_n = 16 * nw + 2 * (lane & 3);

    const int wr = w & 3, wc = w >> 2;
    const int a_row = 16 * wr + (lane & 7) + 8 * ((lane >> 3) & 1);
    const int a_hi = lane >> 4;
    const int a_sw = a_row & 7;
    const int pd_ksub = (lane & 7) + 8 * ((lane >> 3) & 1);
    const int pd_dh = (lane >> 4) & 1;

    const int sa_c = (w < 8) ? (8 * w + (lane >> 2)) : 0;
    const int sa_q = lane & 3;

    float acc[8][4];
    #pragma unroll
    for (int nj = 0; nj < 8; nj++)
        #pragma unroll
        for (int q = 0; q < 4; q++) acc[nj][q] = 0.f;

    __syncthreads();

    for (int i = i0; i < i1; i += TILE) {
        int nb = min(TILE, i1 - i);

        CPWAIT0();
        __syncthreads();
        if (t == 0) *flagn = 0;
        for (int r = t; r < nb * 64; r += NT) {
            int n = r >> 6, e4 = r & 63;
            float4 v = *(const float4*)(rawF + (size_t)r * 4);
            u32 h0, l0, h1, l1;
            split2(v.x, v.y, h0, l0);
            split2(v.z, v.w, h1, l1);
            u32 off = n * 512 + ((e4 * 8) ^ ((n & 7) << 4));
            *(uint2*)((char*)smem + off)         = make_uint2(h0, h1);
            *(uint2*)((char*)smem + 32768 + off) = make_uint2(l0, l1);
        }
        __syncthreads();

        if (i + TILE < i1) {
            int j = i + TILE;
            int nbj = min(TILE, i1 - j);
            for (int r = t; r < nbj * 64; r += NT) {
                int n = r >> 6, e4 = r & 63;
                CP16(rawU + (u32)r * 16u, x + (size_t)(j + n) * D + 4 * e4);
            }
            CPCOMMIT();
        }

        // ---- Phase B (tensor) ----
        {
            float sc[4][4];
            #pragma unroll
            for (int p = 0; p < 4; p++)
                #pragma unroll
                for (int q = 0; q < 4; q++) sc[p][q] = 0.f;
            #pragma unroll
            for (int ks = 0; ks < 16; ks++) {
                const int pe = (ks & 1) * 2;
                u32 aoff = pb_arow * 512 + ((32 * ks + 16 * pb_ae) ^ pb_asw);
                u32 boff = pb_brow * 512 + ((32 * ks + 16 * pb_be) ^ pb_bsw);
                u32 ah0, ah1, ah2, ah3, al0, al1, al2, al3;
                u32 bh0, bh1, bh2, bh3, bl0, bl1, bl2, bl3;
                LDSM4(ah0, ah1, ah2, ah3, qtH + aoff);
                LDSM4(al0, al1, al2, al3, qtL + aoff);
                LDSM4(bh0, bh1, bh2, bh3, xnH + boff);
                LDSM4(bl0, bl1, bl2, bl3, xnL + boff);
                MMA16816(sc[pe],     ah0, ah1, ah2, ah3, bh0, bh1);
                MMA16816(sc[pe + 1], ah0, ah1, ah2, ah3, bh2, bh3);
                MMA16816(sc[pe],     al0, al1, al2, al3, bh0, bh1);
                MMA16816(sc[pe + 1], al0, al1, al2, al3, bh2, bh3);
                MMA16816(sc[pe],     ah0, ah1, ah2, ah3, bl0, bl1);
                MMA16816(sc[pe + 1], ah0, ah1, ah2, ah3, bl2, bl3);
            }
            float ck0 = cKs[wo_c], ck1 = cKs[wo_c + 8];
            #pragma unroll
            for (int h = 0; h < 2; h++) {
                float v0 = sc[h][0] + sc[h + 2][0];
                float v1 = sc[h][1] + sc[h + 2][1];
                float v2 = sc[h][2] + sc[h + 2][2];
                float v3 = sc[h][3] + sc[h + 2][3];
                int n0 = wo_n + 8 * h;
                int m0 = n0 & 31, m1 = (n0 + 1) & 31;
                As[n0 * 64 + 2 * ((wo_c >> 1) ^ m0) + (wo_c & 1)] = v0 + ck0;
                As[(n0 + 1) * 64 + 2 * ((wo_c >> 1) ^ m1) + (wo_c & 1)] = v1 + ck0;
                int c1 = wo_c + 8;
                As[n0 * 64 + 2 * ((c1 >> 1) ^ m0) + (c1 & 1)] = v2 + ck1;
                As[(n0 + 1) * 64 + 2 * ((c1 >> 1) ^ m1) + (c1 & 1)] = v3 + ck1;
            }
        }
        __syncthreads();

        // ---- Phase C ----
        #pragma unroll
        for (int r = 0; r < 2; r++) {
            int nA = 32 * r + w, nB = nA + 16;
            if (nA >= nb) break;
            bool aB = nB < nb;
            int mA_ = nA & 31, mB_ = nB & 31;
            int offA0 = nA * NC + 2 * ((lane >> 1) ^ mA_) + (lane & 1);
            int offA1 = nA * NC + 2 * (((lane >> 1) + 16) ^ mA_) + (lane & 1);
            int offB0 = nB * NC + 2 * ((lane >> 1) ^ mB_) + (lane & 1);
            int offB1 = nB * NC + 2 * (((lane >> 1) + 16) ^ mB_) + (lane & 1);
            float pA0 = As[offA0] * 0.0625f, pA1 = As[offA1] * 0.0625f;
            float pB0 = aB ? As[offB0] * 0.0625f : 0.f;
            float pB1 = aB ? As[offB1] * 0.0625f : 0.f;
            float mxA = fmaxf(pA0, pA1), mxB = fmaxf(pB0, pB1);
            #pragma unroll
            for (int off = 16; off; off >>= 1) {
                mxA = fmaxf(mxA, __shfl_xor_sync(0xffffffffu, mxA, off));
                mxB = fmaxf(mxB, __shfl_xor_sync(0xffffffffu, mxB, off));
            }
            float eA0 = __expf(pA0 - mxA), eA1 = __expf(pA1 - mxA);
            float eB0 = __expf(pB0 - mxB), eB1 = __expf(pB1 - mxB);
            float zA = eA0 + eA1, zB = eB0 + eB1;
            #pragma unroll
            for (int off = 16; off; off >>= 1) {
                zA += __shfl_xor_sync(0xffffffffu, zA, off);
                zB += __shfl_xor_sync(0xffffffffu, zB, off);
            }
            float rzA = __fdividef(1.f, zA), rzB = __fdividef(1.f, zB);
            float avA0 = eA0 * rzA, avA1 = eA1 * rzA;
            float avB0 = eB0 * rzB, avB1 = eB1 * rzB;
            float bvA; int biA;
            if (avA0 >= avA1) { bvA = avA0; biA = lane; } else { bvA = avA1; biA = lane + 32; }
            float bvB; int biB;
            if (avB0 >= avB1) { bvB = avB0; biB = lane; } else { bvB = avB1; biB = lane + 32; }
            #pragma unroll
            for (int off = 16; off; off >>= 1) {
                float ovA = __shfl_xor_sync(0xffffffffu, bvA, off);
                int   oiA = __shfl_xor_sync(0xffffffffu, biA, off);
                float ovB = __shfl_xor_sync(0xffffffffu, bvB, off);
                int   oiB = __shfl_xor_sync(0xffffffffu, biB, off);
                if (ovA > bvA || (ovA == bvA && oiA < biA)) { bvA = ovA; biA = oiA; }
                if (ovB > bvB || (ovB == bvB && oiB < biB)) { bvB = ovB; biB = oiB; }
            }
            As[offA0] = avA0;
            As[offA1] = avA1;
            if (aB) { As[offB0] = avB0; As[offB1] = avB1; }
            float xA0 = (biA == lane) ? -1e30f : avA0;
            float xA1 = (biA == lane + 32) ? -1e30f : avA1;
            float xB0 = (biB == lane) ? -1e30f : avB0;
            float xB1 = (biB == lane + 32) ? -1e30f : avB1;
            float m2A = fmaxf(xA0, xA1), m2B = fmaxf(xB0, xB1);
            #pragma unroll
            for (int off = 16; off; off >>= 1) {
                m2A = fmaxf(m2A, __shfl_xor_sync(0xffffffffu, m2A, off));
                m2B = fmaxf(m2B, __shfl_xor_sync(0xffffffffu, m2B, off));
            }
            if (lane == 0) {
                if (has_arg) {
                    int posA = (i + nA) - s0;
                    argout[(size_t)g * MAXN + posA] = (float)biA;
                    if (aB) {
                        int posB = (i + nB) - s0;
                        argout[(size_t)g * MAXN + posB] = (float)biB;
                    }
                }
                if (bvA - m2A < FLAG_EPS) { int k = atomicAdd(flagn, 1); flagl[k] = nA; }
                if (aB && (bvB - m2B < FLAG_EPS)) { int k = atomicAdd(flagn, 1); flagl[k] = nB; }
            }
        }
        __syncthreads();

        // ---- fallback: exact argmax for flagged nodes (rare) ----
        int nf = *flagn;
        if (has_arg) {
            for (int f = w; f < nf; f += 16) {
                int node = flagl[f];
                const float* xr = x + (size_t)(i + node) * D;
                float fs0 = 0.f, fs1 = 0.f;
                for (int e = 0; e < D; e++) {
                    float xe = __ldg(xr + e);
                    float2 q = *(const float2*)(g_QtT + e * NC + 2 * lane);
                    fs0 = fmaf(xe, q.x, fs0);
                    fs1 = fmaf(xe, q.y, fs1);
                }
                fs0 += cKs[2 * lane];
                fs1 += cKs[2 * lane + 1];
                float p0 = fs0 * 0.0625f, p1 = fs1 * 0.0625f;
                float mx = fmaxf(p0, p1);
                #pragma unroll
                for (int off = 16; off; off >>= 1)
                    mx = fmaxf(mx, __shfl_xor_sync(0xffffffffu, mx, off));
                float e0 = expf(p0 - mx), e1 = expf(p1 - mx);
                float z = e0 + e1;
                #pragma unroll
                for (int off = 16; off; off >>= 1)
                    z += __shfl_xor_sync(0xffffffffu, z, off);
                float av0 = e0 / z, av1 = e1 / z;
                float bv; int bi;
                if (av0 >= av1) { bv = av0; bi = 2 * lane; } else { bv = av1; bi = 2 * lane + 1; }
                #pragma unroll
                for (int off = 16; off; off >>= 1) {
                    float ov = __shfl_xor_sync(0xffffffffu, bv, off);
                    int   oi = __shfl_xor_sync(0xffffffffu, bi, off);
                    if (ov > bv || (ov == bv && oi < bi)) { bv = ov; bi = oi; }
                }
                if (lane == 0) {
                    int pos = (i + node) - s0;
                    argout[(size_t)g * MAXN + pos] = (float)bi;
                }
            }
        }

        // ---- sumA ----
        if (w < 8) {
            int c = sa_c;
            int gidx = c >> 1, par = c & 1;
            float sa = 0.f;
            int nlo = sa_q * 16, nhi = min(nlo + 16, nb);
            for (int n = nlo; n < nhi; n++)
                sa += As[n * NC + 2 * (gidx ^ (n & 31)) + par];
            sa += __shfl_xor_sync(0xffffffffu, sa, 1);
            sa += __shfl_xor_sync(0xffffffffu, sa, 2);
            if (sa_q == 0) sAcc[c] += sa;
        }

        // ---- convert A -> AbfH/AbfL ----
        {
            int c = t >> 3, n0 = (t & 7) * 8;
            u32 ph[4], pl[4];
            #pragma unroll
            for (int q = 0; q < 4; q++) {
                int na = n0 + 2 * q, nb2 = na + 1;
                float va = (na < nb)  ? As[na * NC + 2 * ((c >> 1) ^ (na & 31)) + (c & 1)] : 0.f;
                float vb = (nb2 < nb) ? As[nb2 * NC + 2 * ((c >> 1) ^ (nb2 & 31)) + (c & 1)] : 0.f;
                split2(va, vb, ph[q], pl[q]);
            }
            u32 so = (c * 128 + n0 * 2);
            so = so ^ ((so >> 3) & 0x70);
            *(uint4*)((char*)smem + (abH - sb) + so) = make_uint4(ph[0], ph[1], ph[2], ph[3]);
            *(uint4*)((char*)smem + (abL - sb) + so) = make_uint4(pl[0], pl[1], pl[2], pl[3]);
        }
        __syncthreads();

        // ---- Phase D (tensor) ----
        #pragma unroll
        for (int ks = 0; ks < 4; ks++) {
            u32 a_off = (a_row << 7) + (((2 * ks + a_hi) ^ a_sw) << 4);
            u32 ah0, ah1, ah2, ah3, al0, al1, al2, al3;
            LDSM4(ah0, ah1, ah2, ah3, abH + a_off);
            LDSM4(al0, al1, al2, al3, abL + a_off);
            int k_row = 16 * ks + pd_ksub;
            u32 bbase = k_row * 512;
            u32 bsw = (k_row & 7) << 4;
            #pragma unroll
            for (int jj = 0; jj < 4; jj++) {
                u32 b_off = bbase + ((128 * wc + 32 * jj + 16 * pd_dh) ^ bsw);
                u32 bh0, bh1, bh2, bh3, bl0, bl1, bl2, bl3;
                LDSM4T(bh0, bh1, bh2, bh3, xnH + b_off);
                LDSM4T(bl0, bl1, bl2, bl3, xnL + b_off);
                MMA16816(acc[2 * jj],     ah0, ah1, ah2, ah3, bh0, bh1);
                MMA16816(acc[2 * jj + 1], ah0, ah1, ah2, ah3, bh2, bh3);
                MMA16816(acc[2 * jj],     al0, al1, al2, al3, bh0, bh1);
                MMA16816(acc[2 * jj + 1], al0, al1, al2, al3, bh2, bh3);
                MMA16816(acc[2 * jj],     ah0, ah1, ah2, ah3, bl0, bl1);
                MMA16816(acc[2 * jj + 1], ah0, ah1, ah2, ah3, bl2, bl3);
            }
        }
        __syncthreads();
    }

    // ---- flush accumulators ----
    {
        float* pgb = g_P + (size_t)g * NC * D;
        int r0 = 16 * wr + (lane >> 2);
        #pragma unroll
        for (int nj = 0; nj < 8; nj++) {
            int col = 64 * wc + 8 * nj + 2 * (lane & 3);
            atomicAdd(pgb + (size_t)r0 * D + col,           acc[nj][0]);
            atomicAdd(pgb + (size_t)r0 * D + col + 1,       acc[nj][1]);
            atomicAdd(pgb + (size_t)(r0 + 8) * D + col,     acc[nj][2]);
            atomicAdd(pgb + (size_t)(r0 + 8) * D + col + 1, acc[nj][3]);
        }
    }
    if (t < NC) atomicAdd(&g_sumA[g * NC + t], sAcc[t]);
}

// ---------------- epilogue GEMMs: 16 rows/block, grid 256, f32x2 ----------------
#define ASTR 18
template <int MODE>
__global__ __launch_bounds__(256) void k_gemm(const float* __restrict__ Bmat,
                                              const float* __restrict__ bias,
                                              float* __restrict__ Cout) {
    __shared__ float Ash[D * ASTR];
    int t = threadIdx.x;
    int tx = t & 127, ty = t >> 7;
    int r0 = blockIdx.x * 16;
    const float* Amat = (MODE == 0) ? g_P : g_H;

    {   // stage A [16r][256k] -> Ash[k][r]
        int row = t >> 4, k4 = (t & 15) * 4;
        const float* src = Amat + (size_t)(r0 + row) * D + k4;
        #pragma unroll
        for (int it = 0; it < 4; it++) {
            float4 v = *(const float4*)(src + 64 * it);
            int kb = k4 + 64 * it;
            Ash[(kb + 0) * ASTR + row] = v.x;
            Ash[(kb + 1) * ASTR + row] = v.y;
            Ash[(kb + 2) * ASTR + row] = v.z;
            Ash[(kb + 3) * ASTR + row] = v.w;
        }
    }
    __syncthreads();

    int q0 = 2 * tx;
    int rbase = 8 * ty;
    ull acc2[4][2];
    #pragma unroll
    for (int p = 0; p < 4; p++) { acc2[p][0] = 0ull; acc2[p][1] = 0ull; }

    const float* b0p = Bmat + (size_t)q0 * D;
    const float* b1p = Bmat + (size_t)(q0 + 1) * D;
    for (int k = 0; k < D; k += 4) {
        float4 bv0 = *(const float4*)(b0p + k);
        float4 bv1 = *(const float4*)(b1p + k);
        float b0s[4] = {bv0.x, bv0.y, bv0.z, bv0.w};
        float b1s[4] = {bv1.x, bv1.y, bv1.z, bv1.w};
        #pragma unroll
        for (int kk = 0; kk < 4; kk++) {
            ull bd0, bd1;
            DUP(bd0, b0s[kk]);
            DUP(bd1, b1s[kk]);
            const ull* ar = (const ull*)(Ash + (k + kk) * ASTR + rbase);
            #pragma unroll
            for (int p = 0; p < 4; p++) {
                ull av = ar[p];
                FMA2(acc2[p][0], av, bd0);
                FMA2(acc2[p][1], av, bd1);
            }
        }
    }

    float bias0 = bias[q0], bias1 = bias[q0 + 1];
    #pragma unroll
    for (int p = 0; p < 4; p++) {
        int r = r0 + rbase + 2 * p;
        float v00 = __uint_as_float((u32)(acc2[p][0] & 0xffffffffull));
        float v01 = __uint_as_float((u32)(acc2[p][1] & 0xffffffffull));
        float v10 = __uint_as_float((u32)(acc2[p][0] >> 32));
        float v11 = __uint_as_float((u32)(acc2[p][1] >> 32));
        if (MODE == 0) {
            int c0 = r & (NC - 1), c1 = (r + 1) & (NC - 1);
            float sa0 = g_sumA[r], sa1 = g_sumA[r + 1];
            v00 += g_Q[c0 * D + q0]     + sa0 * bias0;
            v01 += g_Q[c0 * D + q0 + 1] + sa0 * bias1;
            v10 += g_Q[c1 * D + q0]     + sa1 * bias0;
            v11 += g_Q[c1 * D + q0 + 1] + sa1 * bias1;
            *(float2*)(g_H + (size_t)r * D + q0)       = make_float2(v00, v01);
            *(float2*)(g_H + (size_t)(r + 1) * D + q0) = make_float2(v10, v11);
        } else {
            v00 = fmaxf(v00 + bias0, 0.f);
            v01 = fmaxf(v01 + bias1, 0.f);
            v10 = fmaxf(v10 + bias0, 0.f);
            v11 = fmaxf(v11 + bias1, 0.f);
            *(float2*)(Cout + (size_t)r * D + q0)       = make_float2(v00, v01);
            *(float2*)(Cout + (size_t)(r + 1) * D + q0) = make_float2(v10, v11);
        }
    }
}

extern "C" void kernel_launch(void* const* d_in, const int* in_sizes, int n_in,
                              void* d_out, int out_size) {
    const float* x    = (const float*)d_in[0];
    const void*  bat  = d_in[1];
    const float* Qp   = (const float*)d_in[2];
    const float* WQ_w = (const float*)d_in[3];
    const float* WQ_b = (const float*)d_in[4];
    const float* WK_w = (const float*)d_in[5];
    const float* WK_b = (const float*)d_in[6];
    const float* WV_w = (const float*)d_in[7];
    const float* WV_b = (const float*)d_in[8];
    const float* WO_w = (const float*)d_in[9];
    const float* WO_b = (const float*)d_in[10];
    (void)n_in;

    int n_nodes = in_sizes[0] / D;
    float* out = (float*)d_out;
    int has_arg  = out_size >= (NB * NC * D + NB * MAXN);
    int has_mask = out_size >= (NB * NC * D + 2 * NB * MAXN);
    float* argout  = out + NB * NC * D;
    float* maskout = argout + NB * MAXN;

    k_setup<<<NC, 256>>>(bat, n_nodes, Qp, WQ_w, WQ_b, WK_w, WK_b,
                         maskout, argout, has_mask, has_arg);

    const int smem_main = SMEM_FLOATS * (int)sizeof(float);
    cudaFuncSetAttribute(k_main, cudaFuncAttributeMaxDynamicSharedMemorySize, smem_main);
    k_main<<<NB * SPG, NT, smem_main>>>(x, argout, has_arg);

    k_gemm<0><<<(NB * NC) / 16, 256>>>(WV_w, WV_b, nullptr);
    k_gemm<1><<<(NB * NC) / 16, 256>>>(WO_w, WO_b, out);
}

// round 16
// speedup vs baseline: 1.0375x; 1.0375x over previous
#include <cuda_runtime.h>
#include <cuda_bf16.h>

#define D 256
#define NC 64
#define NB 64
#define MAXN 4096
#define SPG 16
#define TILE 64
#define NT 512
#define FLAG_EPS 3e-6f

typedef unsigned long long ull;
typedef unsigned int u32;

#define FMA2(acc, a, b) asm("fma.rn.f32x2 %0, %1, %2, %0;" : "+l"(acc) : "l"(a), "l"(b))
#define DUP(d, x)       asm("mov.b64 %0, {%1, %1};" : "=l"(d) : "r"(__float_as_uint(x)))
#define CVTBF2(r, lo, hi) asm("cvt.rn.bf16x2.f32 %0, %1, %2;" : "=r"(r) : "f"(hi), "f"(lo))

#define CP16(dst, src) \
    asm volatile("cp.async.cg.shared.global [%0], [%1], 16;" :: "r"(dst), "l"(src))
#define CPCOMMIT() asm volatile("cp.async.commit_group;" ::: "memory")
#define CPWAIT0()  asm volatile("cp.async.wait_group 0;" ::: "memory")

#define LDSM4(r0, r1, r2, r3, addr) \
    asm volatile("ldmatrix.sync.aligned.m8n8.x4.shared.b16 {%0,%1,%2,%3}, [%4];" \
                 : "=r"(r0), "=r"(r1), "=r"(r2), "=r"(r3) : "r"(addr))

#define LDSM4T(r0, r1, r2, r3, addr) \
    asm volatile("ldmatrix.sync.aligned.m8n8.x4.trans.shared.b16 {%0,%1,%2,%3}, [%4];" \
                 : "=r"(r0), "=r"(r1), "=r"(r2), "=r"(r3) : "r"(addr))

#define MMA16816(c, a0, a1, a2, a3, b0, b1) \
    asm volatile("mma.sync.aligned.m16n8k16.row.col.f32.bf16.bf16.f32 " \
                 "{%0,%1,%2,%3}, {%4,%5,%6,%7}, {%8,%9}, {%0,%1,%2,%3};" \
                 : "+f"((c)[0]), "+f"((c)[1]), "+f"((c)[2]), "+f"((c)[3]) \
                 : "r"(a0), "r"(a1), "r"(a2), "r"(a3), "r"(b0), "r"(b1))

__device__ int   g_starts[NB + 1];
__device__ float g_Q[NC * D];
__device__ float g_QtT[D * NC];      // [e][c] (fallback)
__device__ u32   g_QtbfH[NC * 128];  // pre-split bf16-hi Qt, k_main smem layout
__device__ u32   g_QtbfL[NC * 128];
__device__ float g_cK[NC];
__device__ float g_P[NB * NC * D];
__device__ float g_sumA[NB * NC];
__device__ float g_H[NB * NC * D];

__device__ __forceinline__ u32 s2u(const void* p) {
    u32 a;
    asm("{ .reg .u64 t; cvta.to.shared.u64 t, %1; cvt.u32.u64 %0, t; }" : "=r"(a) : "l"(p));
    return a;
}

__device__ __forceinline__ void split2(float v0, float v1, u32& hi, u32& lo) {
    CVTBF2(hi, v0, v1);
    float h0 = __uint_as_float(hi << 16);
    float h1 = __uint_as_float(hi & 0xffff0000u);
    CVTBF2(lo, v0 - h0, v1 - h1);
}

__device__ __forceinline__ int lower_bound_batch(const void* batch, int n, int is32, int val) {
    int lo = 0, hi = n;
    while (lo < hi) {
        int mid = (lo + hi) >> 1;
        long long bv = is32 ? (long long)((const int*)batch)[mid]
                            : ((const long long*)batch)[mid];
        if (bv < (long long)val) lo = mid + 1; else hi = mid;
    }
    return lo;
}

// ---------------- fused setup: meta + zero + Q + Qt + Qt split + mask/argzero ----------------
__global__ __launch_bounds__(256) void k_setup(
    const void* __restrict__ batch, int n,
    const float* __restrict__ Qp,
    const float* __restrict__ Wq, const float* __restrict__ bq,
    const float* __restrict__ Wk, const float* __restrict__ bk,
    float* __restrict__ maskout, float* __restrict__ argout,
    int do_mask, int do_arg) {
    __shared__ float shA[D];
    __shared__ float shQ[D];
    __shared__ int shS[2];
    int c = blockIdx.x, e = threadIdx.x;

    // local starts for this block's graph + global table (block 0)
    {
        long long probe = ((const long long*)batch)[n / 4];
        int is32 = (probe < 0 || probe >= NB) ? 1 : 0;
        if (e < 2) shS[e] = lower_bound_batch(batch, n, is32, c + e);
        if (c == 0 && e < NB + 1)
            g_starts[e] = (e < NB) ? lower_bound_batch(batch, n, is32, e) : n;
    }

    // zero g_P slice + g_sumA slice
    {
        float4* pz = (float4*)(g_P + (size_t)c * NC * D);
        float4 z = make_float4(0.f, 0.f, 0.f, 0.f);
        #pragma unroll
        for (int it = 0; it < 16; it++) pz[e + 256 * it] = z;
        if (e < NC) g_sumA[c * NC + e] = 0.f;
    }

    shA[e] = Qp[c * D + e];
    __syncthreads();

    // mask + argout tail zero for graph c
    {
        int cnt = shS[1] - shS[0];
        for (int idx = e; idx < MAXN; idx += 256) {
            if (do_mask) maskout[(size_t)c * MAXN + idx] = (idx < cnt) ? 1.f : 0.f;
            if (do_arg && idx >= cnt) argout[(size_t)c * MAXN + idx] = 0.f;
        }
    }

    {
        float a0 = 0.f, a1 = 0.f, a2 = 0.f, a3 = 0.f;
        #pragma unroll 4
        for (int k = 0; k < D; k += 4) {
            a0 = fmaf(shA[k + 0], Wq[e * D + k + 0], a0);
            a1 = fmaf(shA[k + 1], Wq[e * D + k + 1], a1);
            a2 = fmaf(shA[k + 2], Wq[e * D + k + 2], a2);
            a3 = fmaf(shA[k + 3], Wq[e * D + k + 3], a3);
        }
        float q = ((a0 + a1) + (a2 + a3)) + bq[e];
        shQ[e] = q;
        g_Q[c * D + e] = q;
    }
    __syncthreads();

    {
        float a0 = 0.f, a1 = 0.f;
        #pragma unroll 4
        for (int d = 0; d < D; d += 2) {
            a0 = fmaf(shQ[d + 0], Wk[(d + 0) * D + e], a0);
            a1 = fmaf(shQ[d + 1], Wk[(d + 1) * D + e], a1);
        }
        float v = a0 + a1;
        g_QtT[e * NC + c] = v;
        shA[e] = v;
        if (e == 0) {
            float ck = 0.f;
            for (int d = 0; d < D; d++) ck += shQ[d] * bk[d];
            g_cK[c] = ck;
        }
    }
    __syncthreads();

    if (e < 64) {
        int e4 = e;
        float v0 = shA[4 * e4 + 0], v1 = shA[4 * e4 + 1];
        float v2 = shA[4 * e4 + 2], v3 = shA[4 * e4 + 3];
        u32 h0, l0, h1, l1;
        split2(v0, v1, h0, l0);
        split2(v2, v3, h1, l1);
        int idx = c * 128 + ((2 * e4) ^ ((c & 7) << 2));
        g_QtbfH[idx] = h0; g_QtbfH[idx + 1] = h1;
        g_QtbfL[idx] = l0; g_QtbfL[idx + 1] = l1;
    }
}

// ---------------- main fused kernel (unchanged from R14) ----------------
#define SMEM_FLOATS 57600
extern __shared__ float smem[];

__global__ __launch_bounds__(NT, 1) void k_main(const float* __restrict__ x,
                                                float* __restrict__ argout, int has_arg) {
    float* As   = smem + 32768;
    float* cKs  = smem + 40960;
    float* sAcc = smem + 41024;
    int*   flagn = (int*)(smem + 41088);
    int*   flagl = (int*)(smem + 41089);
    float* rawF = smem + 41216;

    int t = threadIdx.x;
    int g = blockIdx.x / SPG, sl = blockIdx.x % SPG;
    int s0 = g_starts[g], s1 = g_starts[g + 1];
    int cnt = s1 - s0;
    int chunk = (cnt + SPG - 1) / SPG;
    int i0 = s0 + sl * chunk;
    int i1 = min(i0 + chunk, s1);
    if (i0 >= i1) return;  // uniform across block

    u32 sb = s2u(smem);
    const u32 xnH = sb, xnL = sb + 32768;
    const u32 qtH = sb + 65536, qtL = sb + 98304;
    const u32 abH = sb + 147456, abL = sb + 155648;
    const u32 rawU = sb + 41216u * 4u;

    {
        int nbj = min(TILE, i1 - i0);
        for (int r = t; r < nbj * 64; r += NT) {
            int n = r >> 6, e4 = r & 63;
            CP16(rawU + (u32)r * 16u, x + (size_t)(i0 + n) * D + 4 * e4);
        }
        for (int r = t; r < 2048; r += NT) {
            CP16(qtH + (u32)r * 16u, (const char*)g_QtbfH + (size_t)r * 16);
            CP16(qtL + (u32)r * 16u, (const char*)g_QtbfL + (size_t)r * 16);
        }
        CPCOMMIT();
    }

    for (int r = t; r < 16384; r += NT) ((u32*)smem)[r] = 0u;
    if (t < NC) { cKs[t] = g_cK[t]; sAcc[t] = 0.f; }
    if (t == 0) *flagn = 0;

    const int lane = t & 31;
    const int w    = t >> 5;

    const int cw = w & 3, nw = w >> 2;
    const int pb_arow = 16 * cw + (lane & 7) + 8 * ((lane >> 3) & 1);
    const int pb_ae   = (lane >> 4) & 1;
    const int pb_asw  = (pb_arow & 7) << 4;
    const int pb_brow = 16 * nw + (lane & 7) + 8 * ((lane >> 4) & 1);
    const int pb_be   = (lane >> 3) & 1;
    const int pb_bsw  = (pb_brow & 7) << 4;
    const int wo_c = 16 * cw + (lane >> 2);
    const int wo_n = 16 * nw + 2 * (lane & 3);

    const int wr = w & 3, wc = w >> 2;
    const int a_row = 16 * wr + (lane & 7) + 8 * ((lane >> 3) & 1);
    const int a_hi = lane >> 4;
    const int a_sw = a_row & 7;
    const int pd_ksub = (lane & 7) + 8 * ((lane >> 3) & 1);
    const int pd_dh = (lane >> 4) & 1;

    const int sa_c = (w < 8) ? (8 * w + (lane >> 2)) : 0;
    const int sa_q = lane & 3;

    float acc[8][4];
    #pragma unroll
    for (int nj = 0; nj < 8; nj++)
        #pragma unroll
        for (int q = 0; q < 4; q++) acc[nj][q] = 0.f;

    __syncthreads();

    for (int i = i0; i < i1; i += TILE) {
        int nb = min(TILE, i1 - i);

        CPWAIT0();
        __syncthreads();
        if (t == 0) *flagn = 0;
        for (int r = t; r < nb * 64; r += NT) {
            int n = r >> 6, e4 = r & 63;
            float4 v = *(const float4*)(rawF + (size_t)r * 4);
            u32 h0, l0, h1, l1;
            split2(v.x, v.y, h0, l0);
            split2(v.z, v.w, h1, l1);
            u32 off = n * 512 + ((e4 * 8) ^ ((n & 7) << 4));
            *(uint2*)((char*)smem + off)         = make_uint2(h0, h1);
            *(uint2*)((char*)smem + 32768 + off) = make_uint2(l0, l1);
        }
        __syncthreads();

        if (i + TILE < i1) {
            int j = i + TILE;
            int nbj = min(TILE, i1 - j);
            for (int r = t; r < nbj * 64; r += NT) {
                int n = r >> 6, e4 = r & 63;
                CP16(rawU + (u32)r * 16u, x + (size_t)(j + n) * D + 4 * e4);
            }
            CPCOMMIT();
        }

        // ---- Phase B (tensor) ----
        {
            float sc[4][4];
            #pragma unroll
            for (int p = 0; p < 4; p++)
                #pragma unroll
                for (int q = 0; q < 4; q++) sc[p][q] = 0.f;
            #pragma unroll
            for (int ks = 0; ks < 16; ks++) {
                const int pe = (ks & 1) * 2;
                u32 aoff = pb_arow * 512 + ((32 * ks + 16 * pb_ae) ^ pb_asw);
                u32 boff = pb_brow * 512 + ((32 * ks + 16 * pb_be) ^ pb_bsw);
                u32 ah0, ah1, ah2, ah3, al0, al1, al2, al3;
                u32 bh0, bh1, bh2, bh3, bl0, bl1, bl2, bl3;
                LDSM4(ah0, ah1, ah2, ah3, qtH + aoff);
                LDSM4(al0, al1, al2, al3, qtL + aoff);
                LDSM4(bh0, bh1, bh2, bh3, xnH + boff);
                LDSM4(bl0, bl1, bl2, bl3, xnL + boff);
                MMA16816(sc[pe],     ah0, ah1, ah2, ah3, bh0, bh1);
                MMA16816(sc[pe + 1], ah0, ah1, ah2, ah3, bh2, bh3);
                MMA16816(sc[pe],     al0, al1, al2, al3, bh0, bh1);
                MMA16816(sc[pe + 1], al0, al1, al2, al3, bh2, bh3);
                MMA16816(sc[pe],     ah0, ah1, ah2, ah3, bl0, bl1);
                MMA16816(sc[pe + 1], ah0, ah1, ah2, ah3, bl2, bl3);
            }
            float ck0 = cKs[wo_c], ck1 = cKs[wo_c + 8];
            #pragma unroll
            for (int h = 0; h < 2; h++) {
                float v0 = sc[h][0] + sc[h + 2][0];
                float v1 = sc[h][1] + sc[h + 2][1];
                float v2 = sc[h][2] + sc[h + 2][2];
                float v3 = sc[h][3] + sc[h + 2][3];
                int n0 = wo_n + 8 * h;
                int m0 = n0 & 31, m1 = (n0 + 1) & 31;
                As[n0 * 64 + 2 * ((wo_c >> 1) ^ m0) + (wo_c & 1)] = v0 + ck0;
                As[(n0 + 1) * 64 + 2 * ((wo_c >> 1) ^ m1) + (wo_c & 1)] = v1 + ck0;
                int c1 = wo_c + 8;
                As[n0 * 64 + 2 * ((c1 >> 1) ^ m0) + (c1 & 1)] = v2 + ck1;
                As[(n0 + 1) * 64 + 2 * ((c1 >> 1) ^ m1) + (c1 & 1)] = v3 + ck1;
            }
        }
        __syncthreads();

        // ---- Phase C ----
        #pragma unroll
        for (int r = 0; r < 2; r++) {
            int nA = 32 * r + w, nB = nA + 16;
            if (nA >= nb) break;
            bool aB = nB < nb;
            int mA_ = nA & 31, mB_ = nB & 31;
            int offA0 = nA * NC + 2 * ((lane >> 1) ^ mA_) + (lane & 1);
            int offA1 = nA * NC + 2 * (((lane >> 1) + 16) ^ mA_) + (lane & 1);
            int offB0 = nB * NC + 2 * ((lane >> 1) ^ mB_) + (lane & 1);
            int offB1 = nB * NC + 2 * (((lane >> 1) + 16) ^ mB_) + (lane & 1);
            float pA0 = As[offA0] * 0.0625f, pA1 = As[offA1] * 0.0625f;
            float pB0 = aB ? As[offB0] * 0.0625f : 0.f;
            float pB1 = aB ? As[offB1] * 0.0625f : 0.f;
            float mxA = fmaxf(pA0, pA1), mxB = fmaxf(pB0, pB1);
            #pragma unroll
            for (int off = 16; off; off >>= 1) {
                mxA = fmaxf(mxA, __shfl_xor_sync(0xffffffffu, mxA, off));
                mxB = fmaxf(mxB, __shfl_xor_sync(0xffffffffu, mxB, off));
            }
            float eA0 = __expf(pA0 - mxA), eA1 = __expf(pA1 - mxA);
            float eB0 = __expf(pB0 - mxB), eB1 = __expf(pB1 - mxB);
            float zA = eA0 + eA1, zB = eB0 + eB1;
            #pragma unroll
            for (int off = 16; off; off >>= 1) {
                zA += __shfl_xor_sync(0xffffffffu, zA, off);
                zB += __shfl_xor_sync(0xffffffffu, zB, off);
            }
            float rzA = __fdividef(1.f, zA), rzB = __fdividef(1.f, zB);
            float avA0 = eA0 * rzA, avA1 = eA1 * rzA;
            float avB0 = eB0 * rzB, avB1 = eB1 * rzB;
            float bvA; int biA;
            if (avA0 >= avA1) { bvA = avA0; biA = lane; } else { bvA = avA1; biA = lane + 32; }
            float bvB; int biB;
            if (avB0 >= avB1) { bvB = avB0; biB = lane; } else { bvB = avB1; biB = lane + 32; }
            #pragma unroll
            for (int off = 16; off; off >>= 1) {
                float ovA = __shfl_xor_sync(0xffffffffu, bvA, off);
                int   oiA = __shfl_xor_sync(0xffffffffu, biA, off);
                float ovB = __shfl_xor_sync(0xffffffffu, bvB, off);
                int   oiB = __shfl_xor_sync(0xffffffffu, biB, off);
                if (ovA > bvA || (ovA == bvA && oiA < biA)) { bvA = ovA; biA = oiA; }
                if (ovB > bvB || (ovB == bvB && oiB < biB)) { bvB = ovB; biB = oiB; }
            }
            As[offA0] = avA0;
            As[offA1] = avA1;
            if (aB) { As[offB0] = avB0; As[offB1] = avB1; }
            float xA0 = (biA == lane) ? -1e30f : avA0;
            float xA1 = (biA == lane + 32) ? -1e30f : avA1;
            float xB0 = (biB == lane) ? -1e30f : avB0;
            float xB1 = (biB == lane + 32) ? -1e30f : avB1;
            float m2A = fmaxf(xA0, xA1), m2B = fmaxf(xB0, xB1);
            #pragma unroll
            for (int off = 16; off; off >>= 1) {
                m2A = fmaxf(m2A, __shfl_xor_sync(0xffffffffu, m2A, off));
                m2B = fmaxf(m2B, __shfl_xor_sync(0xffffffffu, m2B, off));
            }
            if (lane == 0) {
                if (has_arg) {
                    int posA = (i + nA) - s0;
                    argout[(size_t)g * MAXN + posA] = (float)biA;
                    if (aB) {
                        int posB = (i + nB) - s0;
                        argout[(size_t)g * MAXN + posB] = (float)biB;
                    }
                }
                if (bvA - m2A < FLAG_EPS) { int k = atomicAdd(flagn, 1); flagl[k] = nA; }
                if (aB && (bvB - m2B < FLAG_EPS)) { int k = atomicAdd(flagn, 1); flagl[k] = nB; }
            }
        }
        __syncthreads();

        // ---- fallback: exact argmax for flagged nodes (rare) ----
        int nf = *flagn;
        if (has_arg) {
            for (int f = w; f < nf; f += 16) {
                int node = flagl[f];
                const float* xr = x + (size_t)(i + node) * D;
                float fs0 = 0.f, fs1 = 0.f;
                for (int e = 0; e < D; e++) {
                    float xe = __ldg(xr + e);
                    float2 q = *(const float2*)(g_QtT + e * NC + 2 * lane);
                    fs0 = fmaf(xe, q.x, fs0);
                    fs1 = fmaf(xe, q.y, fs1);
                }
                fs0 += cKs[2 * lane];
                fs1 += cKs[2 * lane + 1];
                float p0 = fs0 * 0.0625f, p1 = fs1 * 0.0625f;
                float mx = fmaxf(p0, p1);
                #pragma unroll
                for (int off = 16; off; off >>= 1)
                    mx = fmaxf(mx, __shfl_xor_sync(0xffffffffu, mx, off));
                float e0 = expf(p0 - mx), e1 = expf(p1 - mx);
                float z = e0 + e1;
                #pragma unroll
                for (int off = 16; off; off >>= 1)
                    z += __shfl_xor_sync(0xffffffffu, z, off);
                float av0 = e0 / z, av1 = e1 / z;
                float bv; int bi;
                if (av0 >= av1) { bv = av0; bi = 2 * lane; } else { bv = av1; bi = 2 * lane + 1; }
                #pragma unroll
                for (int off = 16; off; off >>= 1) {
                    float ov = __shfl_xor_sync(0xffffffffu, bv, off);
                    int   oi = __shfl_xor_sync(0xffffffffu, bi, off);
                    if (ov > bv || (ov == bv && oi < bi)) { bv = ov; bi = oi; }
                }
                if (lane == 0) {
                    int pos = (i + node) - s0;
                    argout[(size_t)g * MAXN + pos] = (float)bi;
                }
            }
        }

        // ---- sumA ----
        if (w < 8) {
            int c = sa_c;
            int gidx = c >> 1, par = c & 1;
            float sa = 0.f;
            int nlo = sa_q * 16, nhi = min(nlo + 16, nb);
            for (int n = nlo; n < nhi; n++)
                sa += As[n * NC + 2 * (gidx ^ (n & 31)) + par];
            sa += __shfl_xor_sync(0xffffffffu, sa, 1);
            sa += __shfl_xor_sync(0xffffffffu, sa, 2);
            if (sa_q == 0) sAcc[c] += sa;
        }

        // ---- convert A -> AbfH/AbfL ----
        {
            int c = t >> 3, n0 = (t & 7) * 8;
            u32 ph[4], pl[4];
            #pragma unroll
            for (int q = 0; q < 4; q++) {
                int na = n0 + 2 * q, nb2 = na + 1;
                float va = (na < nb)  ? As[na * NC + 2 * ((c >> 1) ^ (na & 31)) + (c & 1)] : 0.f;
                float vb = (nb2 < nb) ? As[nb2 * NC + 2 * ((c >> 1) ^ (nb2 & 31)) + (c & 1)] : 0.f;
                split2(va, vb, ph[q], pl[q]);
            }
            u32 so = (c * 128 + n0 * 2);
            so = so ^ ((so >> 3) & 0x70);
            *(uint4*)((char*)smem + (abH - sb) + so) = make_uint4(ph[0], ph[1], ph[2], ph[3]);
            *(uint4*)((char*)smem + (abL - sb) + so) = make_uint4(pl[0], pl[1], pl[2], pl[3]);
        }
        __syncthreads();

        // ---- Phase D (tensor) ----
        #pragma unroll
        for (int ks = 0; ks < 4; ks++) {
            u32 a_off = (a_row << 7) + (((2 * ks + a_hi) ^ a_sw) << 4);
            u32 ah0, ah1, ah2, ah3, al0, al1, al2, al3;
            LDSM4(ah0, ah1, ah2, ah3, abH + a_off);
            LDSM4(al0, al1, al2, al3, abL + a_off);
            int k_row = 16 * ks + pd_ksub;
            u32 bbase = k_row * 512;
            u32 bsw = (k_row & 7) << 4;
            #pragma unroll
            for (int jj = 0; jj < 4; jj++) {
                u32 b_off = bbase + ((128 * wc + 32 * jj + 16 * pd_dh) ^ bsw);
                u32 bh0, bh1, bh2, bh3, bl0, bl1, bl2, bl3;
                LDSM4T(bh0, bh1, bh2, bh3, xnH + b_off);
                LDSM4T(bl0, bl1, bl2, bl3, xnL + b_off);
                MMA16816(acc[2 * jj],     ah0, ah1, ah2, ah3, bh0, bh1);
                MMA16816(acc[2 * jj + 1], ah0, ah1, ah2, ah3, bh2, bh3);
                MMA16816(acc[2 * jj],     al0, al1, al2, al3, bh0, bh1);
                MMA16816(acc[2 * jj + 1], al0, al1, al2, al3, bh2, bh3);
                MMA16816(acc[2 * jj],     ah0, ah1, ah2, ah3, bl0, bl1);
                MMA16816(acc[2 * jj + 1], ah0, ah1, ah2, ah3, bl2, bl3);
            }
        }
        __syncthreads();
    }

    // ---- flush accumulators ----
    {
        float* pgb = g_P + (size_t)g * NC * D;
        int r0 = 16 * wr + (lane >> 2);
        #pragma unroll
        for (int nj = 0; nj < 8; nj++) {
            int col = 64 * wc + 8 * nj + 2 * (lane & 3);
            atomicAdd(pgb + (size_t)r0 * D + col,           acc[nj][0]);
            atomicAdd(pgb + (size_t)r0 * D + col + 1,       acc[nj][1]);
            atomicAdd(pgb + (size_t)(r0 + 8) * D + col,     acc[nj][2]);
            atomicAdd(pgb + (size_t)(r0 + 8) * D + col + 1, acc[nj][3]);
        }
    }
    if (t < NC) atomicAdd(&g_sumA[g * NC + t], sAcc[t]);
}

// ---------------- epilogue GEMMs: 32 rows/block, grid 128, 512 threads ----------------
#define ASTR 34
template <int MODE>
__global__ __launch_bounds__(512) void k_gemm(const float* __restrict__ Bmat,
                                              const float* __restrict__ bias,
                                              float* __restrict__ Cout) {
    __shared__ float Ash[D * ASTR];
    int t = threadIdx.x;
    int tx = t & 255, ty = t >> 8;      // col q = tx, row half = ty
    int r0 = blockIdx.x * 32;
    const float* Amat = (MODE == 0) ? g_P : g_H;

    {   // stage A [32r][256k] -> Ash[k][r] (512 threads)
        int row = t >> 4, k4 = (t & 15) * 4;
        const float* src = Amat + (size_t)(r0 + row) * D + k4;
        #pragma unroll
        for (int it = 0; it < 4; it++) {
            float4 v = *(const float4*)(src + 64 * it);
            int kb = k4 + 64 * it;
            Ash[(kb + 0) * ASTR + row] = v.x;
            Ash[(kb + 1) * ASTR + row] = v.y;
            Ash[(kb + 2) * ASTR + row] = v.z;
            Ash[(kb + 3) * ASTR + row] = v.w;
        }
    }
    __syncthreads();

    int rbase = 16 * ty;
    ull acc2[8];
    #pragma unroll
    for (int p = 0; p < 8; p++) acc2[p] = 0ull;

    const float* bp = Bmat + (size_t)tx * D;
    for (int k = 0; k < D; k += 4) {
        float4 bv = *(const float4*)(bp + k);
        float bs[4] = {bv.x, bv.y, bv.z, bv.w};
        #pragma unroll
        for (int kk = 0; kk < 4; kk++) {
            ull bd;
            DUP(bd, bs[kk]);
            const ull* ar = (const ull*)(Ash + (k + kk) * ASTR + rbase);
            #pragma unroll
            for (int p = 0; p < 8; p++)
                FMA2(acc2[p], ar[p], bd);
        }
    }

    float bias0 = bias[tx];
    #pragma unroll
    for (int p = 0; p < 8; p++) {
        int r = r0 + rbase + 2 * p;
        float v0 = __uint_as_float((u32)(acc2[p] & 0xffffffffull));
        float v1 = __uint_as_float((u32)(acc2[p] >> 32));
        if (MODE == 0) {
            int c0 = r & (NC - 1), c1 = (r + 1) & (NC - 1);
            v0 += g_Q[c0 * D + tx] + g_sumA[r] * bias0;
            v1 += g_Q[c1 * D + tx] + g_sumA[r + 1] * bias0;
            g_H[(size_t)r * D + tx] = v0;
            g_H[(size_t)(r + 1) * D + tx] = v1;
        } else {
            Cout[(size_t)r * D + tx]       = fmaxf(v0 + bias0, 0.f);
            Cout[(size_t)(r + 1) * D + tx] = fmaxf(v1 + bias0, 0.f);
        }
    }
}

extern "C" void kernel_launch(void* const* d_in, const int* in_sizes, int n_in,
                              void* d_out, int out_size) {
    const float* x    = (const float*)d_in[0];
    const void*  bat  = d_in[1];
    const float* Qp   = (const float*)d_in[2];
    const float* WQ_w = (const float*)d_in[3];
    const float* WQ_b = (const float*)d_in[4];
    const float* WK_w = (const float*)d_in[5];
    const float* WK_b = (const float*)d_in[6];
    const float* WV_w = (const float*)d_in[7];
    const float* WV_b = (const float*)d_in[8];
    const float* WO_w = (const float*)d_in[9];
    const float* WO_b = (const float*)d_in[10];
    (void)n_in;

    int n_nodes = in_sizes[0] / D;
    float* out = (float*)d_out;
    int has_arg  = out_size >= (NB * NC * D + NB * MAXN);
    int has_mask = out_size >= (NB * NC * D + 2 * NB * MAXN);
    float* argout  = out + NB * NC * D;
    float* maskout = argout + NB * MAXN;

    k_setup<<<NC, 256>>>(bat, n_nodes, Qp, WQ_w, WQ_b, WK_w, WK_b,
                         maskout, argout, has_mask, has_arg);

    const int smem_main = SMEM_FLOATS * (int)sizeof(float);
    cudaFuncSetAttribute(k_main, cudaFuncAttributeMaxDynamicSharedMemorySize, smem_main);
    k_main<<<NB * SPG, NT, smem_main>>>(x, argout, has_arg);

    k_gemm<0><<<(NB * NC) / 32, 512>>>(WV_w, WV_b, nullptr);
    k_gemm<1><<<(NB * NC) / 32, 512>>>(WO_w, WO_b, out);
}

// round 17
// speedup vs baseline: 1.1229x; 1.0823x over previous
#include <cuda_runtime.h>
#include <cuda_bf16.h>

#define D 256
#define NC 64
#define NB 64
#define MAXN 4096
#define SPG 16
#define TILE 64
#define NT 512
#define FLAG_EPS 3e-6f

typedef unsigned long long ull;
typedef unsigned int u32;

#define FMA2(acc, a, b) asm("fma.rn.f32x2 %0, %1, %2, %0;" : "+l"(acc) : "l"(a), "l"(b))
#define DUP(d, x)       asm("mov.b64 %0, {%1, %1};" : "=l"(d) : "r"(__float_as_uint(x)))
#define CVTBF2(r, lo, hi) asm("cvt.rn.bf16x2.f32 %0, %1, %2;" : "=r"(r) : "f"(hi), "f"(lo))

#define CP16(dst, src) \
    asm volatile("cp.async.cg.shared.global [%0], [%1], 16;" :: "r"(dst), "l"(src))
#define CPCOMMIT() asm volatile("cp.async.commit_group;" ::: "memory")
#define CPWAIT0()  asm volatile("cp.async.wait_group 0;" ::: "memory")

#define LDSM4(r0, r1, r2, r3, addr) \
    asm volatile("ldmatrix.sync.aligned.m8n8.x4.shared.b16 {%0,%1,%2,%3}, [%4];" \
                 : "=r"(r0), "=r"(r1), "=r"(r2), "=r"(r3) : "r"(addr))

#define LDSM4T(r0, r1, r2, r3, addr) \
    asm volatile("ldmatrix.sync.aligned.m8n8.x4.trans.shared.b16 {%0,%1,%2,%3}, [%4];" \
                 : "=r"(r0), "=r"(r1), "=r"(r2), "=r"(r3) : "r"(addr))

#define MMA16816(c, a0, a1, a2, a3, b0, b1) \
    asm volatile("mma.sync.aligned.m16n8k16.row.col.f32.bf16.bf16.f32 " \
                 "{%0,%1,%2,%3}, {%4,%5,%6,%7}, {%8,%9}, {%0,%1,%2,%3};" \
                 : "+f"((c)[0]), "+f"((c)[1]), "+f"((c)[2]), "+f"((c)[3]) \
                 : "r"(a0), "r"(a1), "r"(a2), "r"(a3), "r"(b0), "r"(b1))

__device__ int   g_starts[NB + 1];
__device__ float g_Q[NC * D];
__device__ float g_QtT[D * NC];      // [e][c] (fallback)
__device__ u32   g_QtbfH[NC * 128];  // pre-split bf16 Qt, k_main smem layout
__device__ u32   g_QtbfL[NC * 128];
__device__ float g_cK[NC];
__device__ float g_P[NB * NC * D];
__device__ float g_sumA[NB * NC];

__device__ __forceinline__ u32 s2u(const void* p) {
    u32 a;
    asm("{ .reg .u64 t; cvta.to.shared.u64 t, %1; cvt.u32.u64 %0, t; }" : "=r"(a) : "l"(p));
    return a;
}

__device__ __forceinline__ void split2(float v0, float v1, u32& hi, u32& lo) {
    CVTBF2(hi, v0, v1);
    float h0 = __uint_as_float(hi << 16);
    float h1 = __uint_as_float(hi & 0xffff0000u);
    CVTBF2(lo, v0 - h0, v1 - h1);
}

__device__ __forceinline__ int lower_bound_batch(const void* batch, int n, int is32, int val) {
    int lo = 0, hi = n;
    while (lo < hi) {
        int mid = (lo + hi) >> 1;
        long long bv = is32 ? (long long)((const int*)batch)[mid]
                            : ((const long long*)batch)[mid];
        if (bv < (long long)val) lo = mid + 1; else hi = mid;
    }
    return lo;
}

// ---------------- fused setup (unchanged, proven) ----------------
__global__ __launch_bounds__(256) void k_setup(
    const void* __restrict__ batch, int n,
    const float* __restrict__ Qp,
    const float* __restrict__ Wq, const float* __restrict__ bq,
    const float* __restrict__ Wk, const float* __restrict__ bk,
    float* __restrict__ maskout, float* __restrict__ argout,
    int do_mask, int do_arg) {
    __shared__ float shA[D];
    __shared__ float shQ[D];
    __shared__ int shS[2];
    int c = blockIdx.x, e = threadIdx.x;

    {
        long long probe = ((const long long*)batch)[n / 4];
        int is32 = (probe < 0 || probe >= NB) ? 1 : 0;
        if (e < 2) shS[e] = lower_bound_batch(batch, n, is32, c + e);
        if (c == 0 && e < NB + 1)
            g_starts[e] = (e < NB) ? lower_bound_batch(batch, n, is32, e) : n;
    }

    {
        float4* pz = (float4*)(g_P + (size_t)c * NC * D);
        float4 z = make_float4(0.f, 0.f, 0.f, 0.f);
        #pragma unroll
        for (int it = 0; it < 16; it++) pz[e + 256 * it] = z;
        if (e < NC) g_sumA[c * NC + e] = 0.f;
    }

    shA[e] = Qp[c * D + e];
    __syncthreads();

    {
        int cnt = shS[1] - shS[0];
        for (int idx = e; idx < MAXN; idx += 256) {
            if (do_mask) maskout[(size_t)c * MAXN + idx] = (idx < cnt) ? 1.f : 0.f;
            if (do_arg && idx >= cnt) argout[(size_t)c * MAXN + idx] = 0.f;
        }
    }

    {
        float a0 = 0.f, a1 = 0.f, a2 = 0.f, a3 = 0.f;
        #pragma unroll 4
        for (int k = 0; k < D; k += 4) {
            a0 = fmaf(shA[k + 0], Wq[e * D + k + 0], a0);
            a1 = fmaf(shA[k + 1], Wq[e * D + k + 1], a1);
            a2 = fmaf(shA[k + 2], Wq[e * D + k + 2], a2);
            a3 = fmaf(shA[k + 3], Wq[e * D + k + 3], a3);
        }
        float q = ((a0 + a1) + (a2 + a3)) + bq[e];
        shQ[e] = q;
        g_Q[c * D + e] = q;
    }
    __syncthreads();

    {
        float a0 = 0.f, a1 = 0.f;
        #pragma unroll 4
        for (int d = 0; d < D; d += 2) {
            a0 = fmaf(shQ[d + 0], Wk[(d + 0) * D + e], a0);
            a1 = fmaf(shQ[d + 1], Wk[(d + 1) * D + e], a1);
        }
        float v = a0 + a1;
        g_QtT[e * NC + c] = v;
        shA[e] = v;
        if (e == 0) {
            float ck = 0.f;
            for (int d = 0; d < D; d++) ck += shQ[d] * bk[d];
            g_cK[c] = ck;
        }
    }
    __syncthreads();

    if (e < 64) {
        int e4 = e;
        float v0 = shA[4 * e4 + 0], v1 = shA[4 * e4 + 1];
        float v2 = shA[4 * e4 + 2], v3 = shA[4 * e4 + 3];
        u32 h0, l0, h1, l1;
        split2(v0, v1, h0, l0);
        split2(v2, v3, h1, l1);
        int idx = c * 128 + ((2 * e4) ^ ((c & 7) << 2));
        g_QtbfH[idx] = h0; g_QtbfH[idx + 1] = h1;
        g_QtbfL[idx] = l0; g_QtbfL[idx + 1] = l1;
    }
}

// ---------------- main fused kernel (unchanged from R14, proven) ----------------
#define SMEM_FLOATS 57600
extern __shared__ float smem[];

__global__ __launch_bounds__(NT, 1) void k_main(const float* __restrict__ x,
                                                float* __restrict__ argout, int has_arg) {
    float* As   = smem + 32768;
    float* cKs  = smem + 40960;
    float* sAcc = smem + 41024;
    int*   flagn = (int*)(smem + 41088);
    int*   flagl = (int*)(smem + 41089);
    float* rawF = smem + 41216;

    int t = threadIdx.x;
    int g = blockIdx.x / SPG, sl = blockIdx.x % SPG;
    int s0 = g_starts[g], s1 = g_starts[g + 1];
    int cnt = s1 - s0;
    int chunk = (cnt + SPG - 1) / SPG;
    int i0 = s0 + sl * chunk;
    int i1 = min(i0 + chunk, s1);
    if (i0 >= i1) return;  // uniform across block

    u32 sb = s2u(smem);
    const u32 xnH = sb, xnL = sb + 32768;
    const u32 qtH = sb + 65536, qtL = sb + 98304;
    const u32 abH = sb + 147456, abL = sb + 155648;
    const u32 rawU = sb + 41216u * 4u;

    {
        int nbj = min(TILE, i1 - i0);
        for (int r = t; r < nbj * 64; r += NT) {
            int n = r >> 6, e4 = r & 63;
            CP16(rawU + (u32)r * 16u, x + (size_t)(i0 + n) * D + 4 * e4);
        }
        for (int r = t; r < 2048; r += NT) {
            CP16(qtH + (u32)r * 16u, (const char*)g_QtbfH + (size_t)r * 16);
            CP16(qtL + (u32)r * 16u, (const char*)g_QtbfL + (size_t)r * 16);
        }
        CPCOMMIT();
    }

    for (int r = t; r < 16384; r += NT) ((u32*)smem)[r] = 0u;
    if (t < NC) { cKs[t] = g_cK[t]; sAcc[t] = 0.f; }
    if (t == 0) *flagn = 0;

    const int lane = t & 31;
    const int w    = t >> 5;

    const int cw = w & 3, nw = w >> 2;
    const int pb_arow = 16 * cw + (lane & 7) + 8 * ((lane >> 3) & 1);
    const int pb_ae   = (lane >> 4) & 1;
    const int pb_asw  = (pb_arow & 7) << 4;
    const int pb_brow = 16 * nw + (lane & 7) + 8 * ((lane >> 4) & 1);
    const int pb_be   = (lane >> 3) & 1;
    const int pb_bsw  = (pb_brow & 7) << 4;
    const int wo_c = 16 * cw + (lane >> 2);
    const int wo_n = 16 * nw + 2 * (lane & 3);

    const int wr = w & 3, wc = w >> 2;
    const int a_row = 16 * wr + (lane & 7) + 8 * ((lane >> 3) & 1);
    const int a_hi = lane >> 4;
    const int a_sw = a_row & 7;
    const int pd_ksub = (lane & 7) + 8 * ((lane >> 3) & 1);
    const int pd_dh = (lane >> 4) & 1;

    const int sa_c = (w < 8) ? (8 * w + (lane >> 2)) : 0;
    const int sa_q = lane & 3;

    float acc[8][4];
    #pragma unroll
    for (int nj = 0; nj < 8; nj++)
        #pragma unroll
        for (int q = 0; q < 4; q++) acc[nj][q] = 0.f;

    __syncthreads();

    for (int i = i0; i < i1; i += TILE) {
        int nb = min(TILE, i1 - i);

        CPWAIT0();
        __syncthreads();
        if (t == 0) *flagn = 0;
        for (int r = t; r < nb * 64; r += NT) {
            int n = r >> 6, e4 = r & 63;
            float4 v = *(const float4*)(rawF + (size_t)r * 4);
            u32 h0, l0, h1, l1;
            split2(v.x, v.y, h0, l0);
            split2(v.z, v.w, h1, l1);
            u32 off = n * 512 + ((e4 * 8) ^ ((n & 7) << 4));
            *(uint2*)((char*)smem + off)         = make_uint2(h0, h1);
            *(uint2*)((char*)smem + 32768 + off) = make_uint2(l0, l1);
        }
        __syncthreads();

        if (i + TILE < i1) {
            int j = i + TILE;
            int nbj = min(TILE, i1 - j);
            for (int r = t; r < nbj * 64; r += NT) {
                int n = r >> 6, e4 = r & 63;
                CP16(rawU + (u32)r * 16u, x + (size_t)(j + n) * D + 4 * e4);
            }
            CPCOMMIT();
        }

        // ---- Phase B (tensor) ----
        {
            float sc[4][4];
            #pragma unroll
            for (int p = 0; p < 4; p++)
                #pragma unroll
                for (int q = 0; q < 4; q++) sc[p][q] = 0.f;
            #pragma unroll
            for (int ks = 0; ks < 16; ks++) {
                const int pe = (ks & 1) * 2;
                u32 aoff = pb_arow * 512 + ((32 * ks + 16 * pb_ae) ^ pb_asw);
                u32 boff = pb_brow * 512 + ((32 * ks + 16 * pb_be) ^ pb_bsw);
                u32 ah0, ah1, ah2, ah3, al0, al1, al2, al3;
                u32 bh0, bh1, bh2, bh3, bl0, bl1, bl2, bl3;
                LDSM4(ah0, ah1, ah2, ah3, qtH + aoff);
                LDSM4(al0, al1, al2, al3, qtL + aoff);
                LDSM4(bh0, bh1, bh2, bh3, xnH + boff);
                LDSM4(bl0, bl1, bl2, bl3, xnL + boff);
                MMA16816(sc[pe],     ah0, ah1, ah2, ah3, bh0, bh1);
                MMA16816(sc[pe + 1], ah0, ah1, ah2, ah3, bh2, bh3);
                MMA16816(sc[pe],     al0, al1, al2, al3, bh0, bh1);
                MMA16816(sc[pe + 1], al0, al1, al2, al3, bh2, bh3);
                MMA16816(sc[pe],     ah0, ah1, ah2, ah3, bl0, bl1);
                MMA16816(sc[pe + 1], ah0, ah1, ah2, ah3, bl2, bl3);
            }
            float ck0 = cKs[wo_c], ck1 = cKs[wo_c + 8];
            #pragma unroll
            for (int h = 0; h < 2; h++) {
                float v0 = sc[h][0] + sc[h + 2][0];
                float v1 = sc[h][1] + sc[h + 2][1];
                float v2 = sc[h][2] + sc[h + 2][2];
                float v3 = sc[h][3] + sc[h + 2][3];
                int n0 = wo_n + 8 * h;
                int m0 = n0 & 31, m1 = (n0 + 1) & 31;
                As[n0 * 64 + 2 * ((wo_c >> 1) ^ m0) + (wo_c & 1)] = v0 + ck0;
                As[(n0 + 1) * 64 + 2 * ((wo_c >> 1) ^ m1) + (wo_c & 1)] = v1 + ck0;
                int c1 = wo_c + 8;
                As[n0 * 64 + 2 * ((c1 >> 1) ^ m0) + (c1 & 1)] = v2 + ck1;
                As[(n0 + 1) * 64 + 2 * ((c1 >> 1) ^ m1) + (c1 & 1)] = v3 + ck1;
            }
        }
        __syncthreads();

        // ---- Phase C ----
        #pragma unroll
        for (int r = 0; r < 2; r++) {
            int nA = 32 * r + w, nB = nA + 16;
            if (nA >= nb) break;
            bool aB = nB < nb;
            int mA_ = nA & 31, mB_ = nB & 31;
            int offA0 = nA * NC + 2 * ((lane >> 1) ^ mA_) + (lane & 1);
            int offA1 = nA * NC + 2 * (((lane >> 1) + 16) ^ mA_) + (lane & 1);
            int offB0 = nB * NC + 2 * ((lane >> 1) ^ mB_) + (lane & 1);
            int offB1 = nB * NC + 2 * (((lane >> 1) + 16) ^ mB_) + (lane & 1);
            float pA0 = As[offA0] * 0.0625f, pA1 = As[offA1] * 0.0625f;
            float pB0 = aB ? As[offB0] * 0.0625f : 0.f;
            float pB1 = aB ? As[offB1] * 0.0625f : 0.f;
            float mxA = fmaxf(pA0, pA1), mxB = fmaxf(pB0, pB1);
            #pragma unroll
            for (int off = 16; off; off >>= 1) {
                mxA = fmaxf(mxA, __shfl_xor_sync(0xffffffffu, mxA, off));
                mxB = fmaxf(mxB, __shfl_xor_sync(0xffffffffu, mxB, off));
            }
            float eA0 = __expf(pA0 - mxA), eA1 = __expf(pA1 - mxA);
            float eB0 = __expf(pB0 - mxB), eB1 = __expf(pB1 - mxB);
            float zA = eA0 + eA1, zB = eB0 + eB1;
            #pragma unroll
            for (int off = 16; off; off >>= 1) {
                zA += __shfl_xor_sync(0xffffffffu, zA, off);
                zB += __shfl_xor_sync(0xffffffffu, zB, off);
            }
            float rzA = __fdividef(1.f, zA), rzB = __fdividef(1.f, zB);
            float avA0 = eA0 * rzA, avA1 = eA1 * rzA;
            float avB0 = eB0 * rzB, avB1 = eB1 * rzB;
            float bvA; int biA;
            if (avA0 >= avA1) { bvA = avA0; biA = lane; } else { bvA = avA1; biA = lane + 32; }
            float bvB; int biB;
            if (avB0 >= avB1) { bvB = avB0; biB = lane; } else { bvB = avB1; biB = lane + 32; }
            #pragma unroll
            for (int off = 16; off; off >>= 1) {
                float ovA = __shfl_xor_sync(0xffffffffu, bvA, off);
                int   oiA = __shfl_xor_sync(0xffffffffu, biA, off);
                float ovB = __shfl_xor_sync(0xffffffffu, bvB, off);
                int   oiB = __shfl_xor_sync(0xffffffffu, biB, off);
                if (ovA > bvA || (ovA == bvA && oiA < biA)) { bvA = ovA; biA = oiA; }
                if (ovB > bvB || (ovB == bvB && oiB < biB)) { bvB = ovB; biB = oiB; }
            }
            As[offA0] = avA0;
            As[offA1] = avA1;
            if (aB) { As[offB0] = avB0; As[offB1] = avB1; }
            float xA0 = (biA == lane) ? -1e30f : avA0;
            float xA1 = (biA == lane + 32) ? -1e30f : avA1;
            float xB0 = (biB == lane) ? -1e30f : avB0;
            float xB1 = (biB == lane + 32) ? -1e30f : avB1;
            float m2A = fmaxf(xA0, xA1), m2B = fmaxf(xB0, xB1);
            #pragma unroll
            for (int off = 16; off; off >>= 1) {
                m2A = fmaxf(m2A, __shfl_xor_sync(0xffffffffu, m2A, off));
                m2B = fmaxf(m2B, __shfl_xor_sync(0xffffffffu, m2B, off));
            }
            if (lane == 0) {
                if (has_arg) {
                    int posA = (i + nA) - s0;
                    argout[(size_t)g * MAXN + posA] = (float)biA;
                    if (aB) {
                        int posB = (i + nB) - s0;
                        argout[(size_t)g * MAXN + posB] = (float)biB;
                    }
                }
                if (bvA - m2A < FLAG_EPS) { int k = atomicAdd(flagn, 1); flagl[k] = nA; }
                if (aB && (bvB - m2B < FLAG_EPS)) { int k = atomicAdd(flagn, 1); flagl[k] = nB; }
            }
        }
        __syncthreads();

        // ---- fallback: exact argmax for flagged nodes (rare) ----
        int nf = *flagn;
        if (has_arg) {
            for (int f = w; f < nf; f += 16) {
                int node = flagl[f];
                const float* xr = x + (size_t)(i + node) * D;
                float fs0 = 0.f, fs1 = 0.f;
                for (int e = 0; e < D; e++) {
                    float xe = __ldg(xr + e);
                    float2 q = *(const float2*)(g_QtT + e * NC + 2 * lane);
                    fs0 = fmaf(xe, q.x, fs0);
                    fs1 = fmaf(xe, q.y, fs1);
                }
                fs0 += cKs[2 * lane];
                fs1 += cKs[2 * lane + 1];
                float p0 = fs0 * 0.0625f, p1 = fs1 * 0.0625f;
                float mx = fmaxf(p0, p1);
                #pragma unroll
                for (int off = 16; off; off >>= 1)
                    mx = fmaxf(mx, __shfl_xor_sync(0xffffffffu, mx, off));
                float e0 = expf(p0 - mx), e1 = expf(p1 - mx);
                float z = e0 + e1;
                #pragma unroll
                for (int off = 16; off; off >>= 1)
                    z += __shfl_xor_sync(0xffffffffu, z, off);
                float av0 = e0 / z, av1 = e1 / z;
                float bv; int bi;
                if (av0 >= av1) { bv = av0; bi = 2 * lane; } else { bv = av1; bi = 2 * lane + 1; }
                #pragma unroll
                for (int off = 16; off; off >>= 1) {
                    float ov = __shfl_xor_sync(0xffffffffu, bv, off);
                    int   oi = __shfl_xor_sync(0xffffffffu, bi, off);
                    if (ov > bv || (ov == bv && oi < bi)) { bv = ov; bi = oi; }
                }
                if (lane == 0) {
                    int pos = (i + node) - s0;
                    argout[(size_t)g * MAXN + pos] = (float)bi;
                }
            }
        }

        // ---- sumA ----
        if (w < 8) {
            int c = sa_c;
            int gidx = c >> 1, par = c & 1;
            float sa = 0.f;
            int nlo = sa_q * 16, nhi = min(nlo + 16, nb);
            for (int n = nlo; n < nhi; n++)
                sa += As[n * NC + 2 * (gidx ^ (n & 31)) + par];
            sa += __shfl_xor_sync(0xffffffffu, sa, 1);
            sa += __shfl_xor_sync(0xffffffffu, sa, 2);
            if (sa_q == 0) sAcc[c] += sa;
        }

        // ---- convert A -> AbfH/AbfL ----
        {
            int c = t >> 3, n0 = (t & 7) * 8;
            u32 ph[4], pl[4];
            #pragma unroll
            for (int q = 0; q < 4; q++) {
                int na = n0 + 2 * q, nb2 = na + 1;
                float va = (na < nb)  ? As[na * NC + 2 * ((c >> 1) ^ (na & 31)) + (c & 1)] : 0.f;
                float vb = (nb2 < nb) ? As[nb2 * NC + 2 * ((c >> 1) ^ (nb2 & 31)) + (c & 1)] : 0.f;
                split2(va, vb, ph[q], pl[q]);
            }
            u32 so = (c * 128 + n0 * 2);
            so = so ^ ((so >> 3) & 0x70);
            *(uint4*)((char*)smem + (abH - sb) + so) = make_uint4(ph[0], ph[1], ph[2], ph[3]);
            *(uint4*)((char*)smem + (abL - sb) + so) = make_uint4(pl[0], pl[1], pl[2], pl[3]);
        }
        __syncthreads();

        // ---- Phase D (tensor) ----
        #pragma unroll
        for (int ks = 0; ks < 4; ks++) {
            u32 a_off = (a_row << 7) + (((2 * ks + a_hi) ^ a_sw) << 4);
            u32 ah0, ah1, ah2, ah3, al0, al1, al2, al3;
            LDSM4(ah0, ah1, ah2, ah3, abH + a_off);
            LDSM4(al0, al1, al2, al3, abL + a_off);
            int k_row = 16 * ks + pd_ksub;
            u32 bbase = k_row * 512;
            u32 bsw = (k_row & 7) << 4;
            #pragma unroll
            for (int jj = 0; jj < 4; jj++) {
                u32 b_off = bbase + ((128 * wc + 32 * jj + 16 * pd_dh) ^ bsw);
                u32 bh0, bh1, bh2, bh3, bl0, bl1, bl2, bl3;
                LDSM4T(bh0, bh1, bh2, bh3, xnH + b_off);
                LDSM4T(bl0, bl1, bl2, bl3, xnL + b_off);
                MMA16816(acc[2 * jj],     ah0, ah1, ah2, ah3, bh0, bh1);
                MMA16816(acc[2 * jj + 1], ah0, ah1, ah2, ah3, bh2, bh3);
                MMA16816(acc[2 * jj],     al0, al1, al2, al3, bh0, bh1);
                MMA16816(acc[2 * jj + 1], al0, al1, al2, al3, bh2, bh3);
                MMA16816(acc[2 * jj],     ah0, ah1, ah2, ah3, bl0, bl1);
                MMA16816(acc[2 * jj + 1], ah0, ah1, ah2, ah3, bl2, bl3);
            }
        }
        __syncthreads();
    }

    // ---- flush accumulators ----
    {
        float* pgb = g_P + (size_t)g * NC * D;
        int r0 = 16 * wr + (lane >> 2);
        #pragma unroll
        for (int nj = 0; nj < 8; nj++) {
            int col = 64 * wc + 8 * nj + 2 * (lane & 3);
            atomicAdd(pgb + (size_t)r0 * D + col,           acc[nj][0]);
            atomicAdd(pgb + (size_t)r0 * D + col + 1,       acc[nj][1]);
            atomicAdd(pgb + (size_t)(r0 + 8) * D + col,     acc[nj][2]);
            atomicAdd(pgb + (size_t)(r0 + 8) * D + col + 1, acc[nj][3]);
        }
    }
    if (t < NC) atomicAdd(&g_sumA[g * NC + t], sAcc[t]);
}

// ---------------- fused epilogue: out = relu((P@Wv^T + Q + sumA*bv) @ Wo^T + bo) ----------------
// grid 128 x 256 threads; thread (tx 0..127, ty 0..1): cols {2tx,2tx+1}, rows 16ty..+16.
// Ash/Hsh: [k][r] stride 34.  Bsh: [kk][q] stride 258 (k-tile 32, coalesced stage).
#define ASTR 34
#define BSTR 258
#define GF_A 0
#define GF_H 8704
#define GF_B 17408
#define GF_TOT (17408 + 32 * BSTR)   // 25664 floats = 102656 B

__global__ __launch_bounds__(256) void k_gemm_fused(
    const float* __restrict__ Wv, const float* __restrict__ bv,
    const float* __restrict__ Wo, const float* __restrict__ bo,
    float* __restrict__ Cout) {
    float* Ash = smem + GF_A;
    float* Hsh = smem + GF_H;
    float* Bsh = smem + GF_B;
    int t = threadIdx.x;
    int tx = t & 127, ty = t >> 7;
    int r0 = blockIdx.x * 32;
    int q0 = 2 * tx;
    int rbase = 16 * ty;
    const int bq = t >> 3, bk4 = (t & 7) * 4;

    {   // stage P -> Ash[k][r]
        int row = t >> 3, k4 = (t & 7) * 4;
        const float* src = g_P + (size_t)(r0 + row) * D + k4;
        #pragma unroll
        for (int it = 0; it < 8; it++) {
            float4 v = *(const float4*)(src + 32 * it);
            int kb = k4 + 32 * it;
            Ash[(kb + 0) * ASTR + row] = v.x;
            Ash[(kb + 1) * ASTR + row] = v.y;
            Ash[(kb + 2) * ASTR + row] = v.z;
            Ash[(kb + 3) * ASTR + row] = v.w;
        }
    }

    for (int pass = 0; pass < 2; pass++) {
        const float* Asrc = (pass == 0) ? Ash : Hsh;
        const float* Bp   = (pass == 0) ? Wv : Wo;
        ull acc2[8][2];
        #pragma unroll
        for (int p = 0; p < 8; p++) { acc2[p][0] = 0ull; acc2[p][1] = 0ull; }

        for (int kt = 0; kt < D; kt += 32) {
            __syncthreads();   // Asrc ready (first iter) / Bsh consumed (later iters)
            {   // stage Bsh[kk][q] for kk in [0,32): coalesced LDG, conflict-free STS
                #pragma unroll
                for (int it = 0; it < 8; it++) {
                    int q = bq + 32 * it;
                    float4 v = *(const float4*)(Bp + (size_t)q * D + kt + bk4);
                    Bsh[(bk4 + 0) * BSTR + q] = v.x;
                    Bsh[(bk4 + 1) * BSTR + q] = v.y;
                    Bsh[(bk4 + 2) * BSTR + q] = v.z;
                    Bsh[(bk4 + 3) * BSTR + q] = v.w;
                }
            }
            __syncthreads();

            #pragma unroll 8
            for (int kk = 0; kk < 32; kk++) {
                float f0 = Bsh[kk * BSTR + q0];
                float f1 = Bsh[kk * BSTR + q0 + 1];
                ull bd0, bd1;
                DUP(bd0, f0);
                DUP(bd1, f1);
                const ull* ar = (const ull*)(Asrc + (kt + kk) * ASTR + rbase);
                #pragma unroll
                for (int p = 0; p < 8; p++) {
                    ull av = ar[p];
                    FMA2(acc2[p][0], av, bd0);
                    FMA2(acc2[p][1], av, bd1);
                }
            }
        }

        if (pass == 0) {
            float bias0 = bv[q0], bias1 = bv[q0 + 1];
            __syncthreads();   // everyone done reading Ash region? (Hsh separate; sync for Bsh ordering)
            #pragma unroll
            for (int p = 0; p < 8; p++) {
                int rl = rbase + 2 * p;
                int r = r0 + rl;
                int c0 = r & (NC - 1), c1 = (r + 1) & (NC - 1);
                float sa0 = g_sumA[r], sa1 = g_sumA[r + 1];
                float v00 = __uint_as_float((u32)(acc2[p][0] & 0xffffffffull))
                          + g_Q[c0 * D + q0] + sa0 * bias0;
                float v01 = __uint_as_float((u32)(acc2[p][1] & 0xffffffffull))
                          + g_Q[c0 * D + q0 + 1] + sa0 * bias1;
                float v10 = __uint_as_float((u32)(acc2[p][0] >> 32))
                          + g_Q[c1 * D + q0] + sa1 * bias0;
                float v11 = __uint_as_float((u32)(acc2[p][1] >> 32))
                          + g_Q[c1 * D + q0 + 1] + sa1 * bias1;
                Hsh[q0 * ASTR + rl]           = v00;
                Hsh[(q0 + 1) * ASTR + rl]     = v01;
                Hsh[q0 * ASTR + rl + 1]       = v10;
                Hsh[(q0 + 1) * ASTR + rl + 1] = v11;
            }
        } else {
            float bias0 = bo[q0], bias1 = bo[q0 + 1];
            #pragma unroll
            for (int p = 0; p < 8; p++) {
                int r = r0 + rbase + 2 * p;
                float v00 = fmaxf(__uint_as_float((u32)(acc2[p][0] & 0xffffffffull)) + bias0, 0.f);
                float v01 = fmaxf(__uint_as_float((u32)(acc2[p][1] & 0xffffffffull)) + bias1, 0.f);
                float v10 = fmaxf(__uint_as_float((u32)(acc2[p][0] >> 32)) + bias0, 0.f);
                float v11 = fmaxf(__uint_as_float((u32)(acc2[p][1] >> 32)) + bias1, 0.f);
                *(float2*)(Cout + (size_t)r * D + q0)       = make_float2(v00, v01);
                *(float2*)(Cout + (size_t)(r + 1) * D + q0) = make_float2(v10, v11);
            }
        }
        __syncthreads();   // Hsh fully written before pass 2 reads
    }
}

extern "C" void kernel_launch(void* const* d_in, const int* in_sizes, int n_in,
                              void* d_out, int out_size) {
    const float* x    = (const float*)d_in[0];
    const void*  bat  = d_in[1];
    const float* Qp   = (const float*)d_in[2];
    const float* WQ_w = (const float*)d_in[3];
    const float* WQ_b = (const float*)d_in[4];
    const float* WK_w = (const float*)d_in[5];
    const float* WK_b = (const float*)d_in[6];
    const float* WV_w = (const float*)d_in[7];
    const float* WV_b = (const float*)d_in[8];
    const float* WO_w = (const float*)d_in[9];
    const float* WO_b = (const float*)d_in[10];
    (void)n_in;

    int n_nodes = in_sizes[0] / D;
    float* out = (float*)d_out;
    int has_arg  = out_size >= (NB * NC * D + NB * MAXN);
    int has_mask = out_size >= (NB * NC * D + 2 * NB * MAXN);
    float* argout  = out + NB * NC * D;
    float* maskout = argout + NB * MAXN;

    k_setup<<<NC, 256>>>(bat, n_nodes, Qp, WQ_w, WQ_b, WK_w, WK_b,
                         maskout, argout, has_mask, has_arg);

    const int smem_main = SMEM_FLOATS * (int)sizeof(float);
    cudaFuncSetAttribute(k_main, cudaFuncAttributeMaxDynamicSharedMemorySize, smem_main);
    k_main<<<NB * SPG, NT, smem_main>>>(x, argout, has_arg);

    const int smem_gf = GF_TOT * (int)sizeof(float);
    cudaFuncSetAttribute(k_gemm_fused, cudaFuncAttributeMaxDynamicSharedMemorySize, smem_gf);
    k_gemm_fused<<<(NB * NC) / 32, 256, smem_gf>>>(WV_w, WV_b, WO_w, WO_b, out);
}